// round 2
// baseline (speedup 1.0000x reference)
#include <cuda_runtime.h>
#include <cuda_bf16.h>

// GraphSAGE 2-layer, fp32.
//   L1: agg1 = segmean(x) [64]; h = relu(agg1@W1l + x@W1r + b1) [128]
//   L2: t = h@W2l [64]; hr = h@W2r [64]; out = segmean(t) + hr + b2
// (segmean/transform commute since mean is linear per-row.)

#define MAXN 100000
#define MAXE 1600000

__device__ int   g_is64;
__device__ int   g_src[MAXE];
__device__ int   g_dst[MAXE];
__device__ int   g_cnt[MAXN];
__device__ int   g_row[MAXN + 1];
__device__ int   g_next[MAXN];
__device__ int   g_col[MAXE];
__device__ int   g_bs[1024];
__device__ int   g_bo[1024];
__device__ float g_agg[MAXN * 64];
__device__ float g_h[MAXN * 128];
__device__ float g_t[MAXN * 64];

// ---------------- edge dtype detect + convert ----------------

__global__ void k_detect(const int* __restrict__ ei32, int E) {
    if (threadIdx.x == 0 && blockIdx.x == 0) {
        // int64 data with node ids < 2^31: every odd int32 word (high half) is 0.
        // int32 data: odd words are random node ids; all-zero chance ~0.
        int s = 0;
        #pragma unroll
        for (int i = 0; i < 64; i++) s |= ei32[2 * i + 1];
        g_is64 = (s == 0) ? 1 : 0;
    }
}

__global__ void k_convert(const void* __restrict__ ei, int E, int n) {
    int e = blockIdx.x * blockDim.x + threadIdx.x;
    if (e >= E) return;
    int s, d;
    if (g_is64) {
        const long long* p = (const long long*)ei;
        s = (int)p[e];
        d = (int)p[E + e];
    } else {
        const int* p = (const int*)ei;
        s = p[e];
        d = p[E + e];
    }
    // defensive clamp (no-op for valid data)
    s = min(max(s, 0), n - 1);
    d = min(max(d, 0), n - 1);
    g_src[e] = s;
    g_dst[e] = d;
}

// ---------------- CSR build ----------------

__global__ void k_zero(int n) {
    int i = blockIdx.x * blockDim.x + threadIdx.x;
    if (i < n) g_cnt[i] = 0;
}

__global__ void k_hist(int E) {
    int e = blockIdx.x * blockDim.x + threadIdx.x;
    if (e < E) atomicAdd(&g_cnt[g_dst[e]], 1);
}

__global__ void k_scanA(int n) {
    __shared__ int s[1024];
    int i = blockIdx.x * 1024 + threadIdx.x;
    int v = (i < n) ? g_cnt[i] : 0;
    s[threadIdx.x] = v;
    __syncthreads();
    for (int off = 1; off < 1024; off <<= 1) {
        int t = (threadIdx.x >= off) ? s[threadIdx.x - off] : 0;
        __syncthreads();
        s[threadIdx.x] += t;
        __syncthreads();
    }
    if (i < n) g_row[i] = s[threadIdx.x] - v;  // exclusive within block
    if (threadIdx.x == 1023) g_bs[blockIdx.x] = s[1023];
}

__global__ void k_scanB(int nb) {
    __shared__ int s[1024];
    int v = (threadIdx.x < nb) ? g_bs[threadIdx.x] : 0;
    s[threadIdx.x] = v;
    __syncthreads();
    for (int off = 1; off < 1024; off <<= 1) {
        int t = (threadIdx.x >= off) ? s[threadIdx.x - off] : 0;
        __syncthreads();
        s[threadIdx.x] += t;
        __syncthreads();
    }
    g_bo[threadIdx.x] = s[threadIdx.x] - v;  // exclusive block offsets
}

__global__ void k_scanC(int n, int E) {
    int i = blockIdx.x * blockDim.x + threadIdx.x;
    if (i < n) {
        int r = g_row[i] + g_bo[i >> 10];
        g_row[i] = r;
        g_next[i] = r;
    }
    if (i == 0) g_row[n] = E;
}

__global__ void k_fill(int E) {
    int e = blockIdx.x * blockDim.x + threadIdx.x;
    if (e < E) {
        int s = g_src[e];
        int d = g_dst[e];
        int p = atomicAdd(&g_next[d], 1);
        g_col[p] = s;
    }
}

// ---------------- segment mean (64 features, 1 warp / node) ----------------

__global__ void k_aggmean(const float* __restrict__ src, float* __restrict__ dstArr, int n) {
    int w = (blockIdx.x * blockDim.x + threadIdx.x) >> 5;
    int lane = threadIdx.x & 31;
    if (w >= n) return;
    int beg = g_row[w], end = g_row[w + 1];
    const float2* s2 = (const float2*)src;
    float sx = 0.f, sy = 0.f;
    int j = beg;
    for (; j + 4 <= end; j += 4) {
        int c0 = __ldg(&g_col[j]);
        int c1 = __ldg(&g_col[j + 1]);
        int c2 = __ldg(&g_col[j + 2]);
        int c3 = __ldg(&g_col[j + 3]);
        float2 v0 = __ldg(&s2[c0 * 32 + lane]);
        float2 v1 = __ldg(&s2[c1 * 32 + lane]);
        float2 v2 = __ldg(&s2[c2 * 32 + lane]);
        float2 v3 = __ldg(&s2[c3 * 32 + lane]);
        sx += v0.x + v1.x + v2.x + v3.x;
        sy += v0.y + v1.y + v2.y + v3.y;
    }
    for (; j < end; j++) {
        int c = __ldg(&g_col[j]);
        float2 v = __ldg(&s2[c * 32 + lane]);
        sx += v.x;
        sy += v.y;
    }
    int deg = end - beg;
    float inv = 1.0f / (float)(deg > 0 ? deg : 1);
    float2 o;
    o.x = sx * inv;
    o.y = sy * inv;
    ((float2*)dstArr)[w * 32 + lane] = o;
}

__global__ void k_aggmean_add(const float* __restrict__ src, float* __restrict__ out, int n) {
    int w = (blockIdx.x * blockDim.x + threadIdx.x) >> 5;
    int lane = threadIdx.x & 31;
    if (w >= n) return;
    int beg = g_row[w], end = g_row[w + 1];
    const float2* s2 = (const float2*)src;
    float sx = 0.f, sy = 0.f;
    int j = beg;
    for (; j + 4 <= end; j += 4) {
        int c0 = __ldg(&g_col[j]);
        int c1 = __ldg(&g_col[j + 1]);
        int c2 = __ldg(&g_col[j + 2]);
        int c3 = __ldg(&g_col[j + 3]);
        float2 v0 = __ldg(&s2[c0 * 32 + lane]);
        float2 v1 = __ldg(&s2[c1 * 32 + lane]);
        float2 v2 = __ldg(&s2[c2 * 32 + lane]);
        float2 v3 = __ldg(&s2[c3 * 32 + lane]);
        sx += v0.x + v1.x + v2.x + v3.x;
        sy += v0.y + v1.y + v2.y + v3.y;
    }
    for (; j < end; j++) {
        int c = __ldg(&g_col[j]);
        float2 v = __ldg(&s2[c * 32 + lane]);
        sx += v.x;
        sy += v.y;
    }
    int deg = end - beg;
    float inv = 1.0f / (float)(deg > 0 ? deg : 1);
    float2* o2 = (float2*)out;
    float2 cur = o2[w * 32 + lane];
    cur.x += sx * inv;
    cur.y += sy * inv;
    o2[w * 32 + lane] = cur;
}

// ---------------- GEMM layer 1: h = relu([agg1|x] @ [W1l;W1r] + b1) ----------------
// tile 64 rows x 128 cols, K=128. 128 threads, 8x8 micro-tile.

__global__ void __launch_bounds__(128, 1)
k_gemm1(const float* __restrict__ agg, const float* __restrict__ x,
        const float* __restrict__ Wl, const float* __restrict__ Wr,
        const float* __restrict__ b, float* __restrict__ h, int n) {
    extern __shared__ float sm[];
    float* As = sm;             // 64 * 128
    float* Ws = sm + 64 * 128;  // 128 * 128
    float4* As4 = (float4*)As;
    float4* Ws4 = (float4*)Ws;
    int tid = threadIdx.x;
    int row0 = blockIdx.x * 64;

    const float4* L4 = (const float4*)Wl;
    const float4* R4 = (const float4*)Wr;
    #pragma unroll
    for (int i = tid; i < 64 * 32; i += 128) {
        Ws4[i] = __ldg(&L4[i]);
        Ws4[64 * 32 + i] = __ldg(&R4[i]);
    }
    const float4* A0 = (const float4*)agg;
    const float4* A1 = (const float4*)x;
    #pragma unroll
    for (int i = tid; i < 64 * 32; i += 128) {
        int r = i >> 5, c = i & 31;
        int row = row0 + r;
        float4 v = make_float4(0.f, 0.f, 0.f, 0.f);
        if (row < n)
            v = (c < 16) ? __ldg(&A0[row * 16 + c]) : __ldg(&A1[row * 16 + (c - 16)]);
        As4[i] = v;
    }
    __syncthreads();

    int tx = tid & 15;  // col group (8 cols)
    int ty = tid >> 4;  // row group (8 rows)
    float acc[8][8];
    #pragma unroll
    for (int r = 0; r < 8; r++)
        #pragma unroll
        for (int c = 0; c < 8; c++) acc[r][c] = 0.f;

    #pragma unroll 4
    for (int k = 0; k < 128; k++) {
        float a[8];
        #pragma unroll
        for (int r = 0; r < 8; r++) a[r] = As[(ty * 8 + r) * 128 + k];
        float4 w0 = Ws4[k * 32 + tx * 2];
        float4 w1 = Ws4[k * 32 + tx * 2 + 1];
        float w[8] = {w0.x, w0.y, w0.z, w0.w, w1.x, w1.y, w1.z, w1.w};
        #pragma unroll
        for (int r = 0; r < 8; r++)
            #pragma unroll
            for (int c = 0; c < 8; c++) acc[r][c] += a[r] * w[c];
    }

    float bb[8];
    #pragma unroll
    for (int c = 0; c < 8; c++) bb[c] = __ldg(&b[tx * 8 + c]);
    #pragma unroll
    for (int r = 0; r < 8; r++) {
        int row = row0 + ty * 8 + r;
        if (row < n) {
            float4 o0, o1;
            o0.x = fmaxf(acc[r][0] + bb[0], 0.f);
            o0.y = fmaxf(acc[r][1] + bb[1], 0.f);
            o0.z = fmaxf(acc[r][2] + bb[2], 0.f);
            o0.w = fmaxf(acc[r][3] + bb[3], 0.f);
            o1.x = fmaxf(acc[r][4] + bb[4], 0.f);
            o1.y = fmaxf(acc[r][5] + bb[5], 0.f);
            o1.z = fmaxf(acc[r][6] + bb[6], 0.f);
            o1.w = fmaxf(acc[r][7] + bb[7], 0.f);
            float4* hp = (float4*)&h[row * 128 + tx * 8];
            hp[0] = o0;
            hp[1] = o1;
        }
    }
}

// ---------------- GEMM layer 2: [t|hr] = h @ [W2l|W2r]; out = hr + b2 ----------------

__global__ void __launch_bounds__(128, 1)
k_gemm2(const float* __restrict__ h,
        const float* __restrict__ Wl, const float* __restrict__ Wr,
        const float* __restrict__ b, float* __restrict__ t, float* __restrict__ out, int n) {
    extern __shared__ float sm[];
    float* As = sm;             // 64 * 128
    float* Ws = sm + 64 * 128;  // 128 * 128
    float4* As4 = (float4*)As;
    float4* Ws4 = (float4*)Ws;
    int tid = threadIdx.x;
    int row0 = blockIdx.x * 64;

    const float4* L4 = (const float4*)Wl;
    const float4* R4 = (const float4*)Wr;
    #pragma unroll
    for (int i = tid; i < 128 * 32; i += 128) {
        int k = i >> 5, c = i & 31;
        Ws4[i] = (c < 16) ? __ldg(&L4[k * 16 + c]) : __ldg(&R4[k * 16 + (c - 16)]);
    }
    const float4* H4 = (const float4*)h;
    #pragma unroll
    for (int i = tid; i < 64 * 32; i += 128) {
        int r = i >> 5, c = i & 31;
        int row = row0 + r;
        float4 v = make_float4(0.f, 0.f, 0.f, 0.f);
        if (row < n) v = __ldg(&H4[row * 32 + c]);
        As4[i] = v;
    }
    __syncthreads();

    int tx = tid & 15;
    int ty = tid >> 4;
    float acc[8][8];
    #pragma unroll
    for (int r = 0; r < 8; r++)
        #pragma unroll
        for (int c = 0; c < 8; c++) acc[r][c] = 0.f;

    #pragma unroll 4
    for (int k = 0; k < 128; k++) {
        float a[8];
        #pragma unroll
        for (int r = 0; r < 8; r++) a[r] = As[(ty * 8 + r) * 128 + k];
        float4 w0 = Ws4[k * 32 + tx * 2];
        float4 w1 = Ws4[k * 32 + tx * 2 + 1];
        float w[8] = {w0.x, w0.y, w0.z, w0.w, w1.x, w1.y, w1.z, w1.w};
        #pragma unroll
        for (int r = 0; r < 8; r++)
            #pragma unroll
            for (int c = 0; c < 8; c++) acc[r][c] += a[r] * w[c];
    }

    if (tx < 8) {
        // t region: global cols 0..63 (h @ W2l, no bias — bias rides on hr path)
        #pragma unroll
        for (int r = 0; r < 8; r++) {
            int row = row0 + ty * 8 + r;
            if (row < n) {
                float4 o0 = make_float4(acc[r][0], acc[r][1], acc[r][2], acc[r][3]);
                float4 o1 = make_float4(acc[r][4], acc[r][5], acc[r][6], acc[r][7]);
                float4* tp = (float4*)&t[row * 64 + tx * 8];
                tp[0] = o0;
                tp[1] = o1;
            }
        }
    } else {
        int colb = tx * 8 - 64;  // 0..56
        float bb[8];
        #pragma unroll
        for (int c = 0; c < 8; c++) bb[c] = __ldg(&b[colb + c]);
        #pragma unroll
        for (int r = 0; r < 8; r++) {
            int row = row0 + ty * 8 + r;
            if (row < n) {
                float4 o0 = make_float4(acc[r][0] + bb[0], acc[r][1] + bb[1],
                                        acc[r][2] + bb[2], acc[r][3] + bb[3]);
                float4 o1 = make_float4(acc[r][4] + bb[4], acc[r][5] + bb[5],
                                        acc[r][6] + bb[6], acc[r][7] + bb[7]);
                float4* op = (float4*)&out[row * 64 + colb];
                op[0] = o0;
                op[1] = o1;
            }
        }
    }
}

// ---------------- launch ----------------

extern "C" void kernel_launch(void* const* d_in, const int* in_sizes, int n_in,
                              void* d_out, int out_size) {
    const float* x = (const float*)d_in[0];
    const void* ei = d_in[1];
    const float* W1l = (const float*)d_in[2];
    const float* W1r = (const float*)d_in[3];
    const float* b1 = (const float*)d_in[4];
    const float* W2l = (const float*)d_in[5];
    const float* W2r = (const float*)d_in[6];
    const float* b2 = (const float*)d_in[7];
    float* out = (float*)d_out;

    int n = in_sizes[0] / 64;
    int E = in_sizes[1] / 2;

    float* agg;  cudaGetSymbolAddress((void**)&agg, g_agg);
    float* h;    cudaGetSymbolAddress((void**)&h, g_h);
    float* t;    cudaGetSymbolAddress((void**)&t, g_t);

    cudaFuncSetAttribute(k_gemm1, cudaFuncAttributeMaxDynamicSharedMemorySize, 98304);
    cudaFuncSetAttribute(k_gemm2, cudaFuncAttributeMaxDynamicSharedMemorySize, 98304);

    int nb = (n + 1023) / 1024;

    k_detect<<<1, 32>>>((const int*)ei, E);
    k_convert<<<(E + 255) / 256, 256>>>(ei, E, n);

    k_zero<<<(n + 255) / 256, 256>>>(n);
    k_hist<<<(E + 255) / 256, 256>>>(E);
    k_scanA<<<nb, 1024>>>(n);
    k_scanB<<<1, 1024>>>(nb);
    k_scanC<<<(n + 255) / 256, 256>>>(n, E);
    k_fill<<<(E + 255) / 256, 256>>>(E);

    // layer 1
    k_aggmean<<<(n * 32 + 255) / 256, 256>>>(x, agg, n);
    k_gemm1<<<(n + 63) / 64, 128, 98304>>>(agg, x, W1l, W1r, b1, h, n);

    // layer 2
    k_gemm2<<<(n + 63) / 64, 128, 98304>>>(h, W2l, W2r, b2, t, out, n);
    k_aggmean_add<<<(n * 32 + 255) / 256, 256>>>(t, out, n);
}